// round 15
// baseline (speedup 1.0000x reference)
#include <cuda_runtime.h>
#include <cuda_bf16.h>
#include <cstdint>
#include <math.h>

#define D_MODEL   1024
#define NUM_HEADS 16
#define HEAD_DIM  64
#define BATCH     2
#define SEQ       2048
#define NROWS     (BATCH * SEQ)   // 4096
#define D2        ((size_t)D_MODEL * D_MODEL)

// ---------------------------------------------------------------------------
// Scratch (device globals; no runtime allocation allowed)
// ---------------------------------------------------------------------------
__device__ float g_AO[(size_t)NROWS * D_MODEL];
__device__ __nv_bfloat16 g_xh[(size_t)NROWS * D_MODEL];
__device__ __nv_bfloat16 g_xl[(size_t)NROWS * D_MODEL];
__device__ __nv_bfloat16 g_wh[3 * D2];
__device__ __nv_bfloat16 g_wl[3 * D2];
__device__ __nv_bfloat16 g_Qh[(size_t)NROWS * D_MODEL];
__device__ __nv_bfloat16 g_Ql[(size_t)NROWS * D_MODEL];
__device__ __nv_bfloat16 g_Kh[(size_t)NROWS * D_MODEL];
__device__ __nv_bfloat16 g_Kl[(size_t)NROWS * D_MODEL];
__device__ __nv_bfloat16 g_Vh[(size_t)NROWS * D_MODEL];
__device__ __nv_bfloat16 g_Vl[(size_t)NROWS * D_MODEL];
__device__ float g_m [(size_t)BATCH * NUM_HEADS * SEQ];
__device__ float g_il[(size_t)BATCH * NUM_HEADS * SEQ];

// ---------------------------------------------------------------------------
// HMMA helpers (mma.sync bf16, base sm_103 target)
// ---------------------------------------------------------------------------
__device__ __forceinline__ uint32_t smem_u32(const void* p) {
    uint32_t a;
    asm("{ .reg .u64 t; cvta.to.shared.u64 t, %1; cvt.u32.u64 %0, t; }"
        : "=r"(a) : "l"(p));
    return a;
}
__device__ __forceinline__ void ldmatrix_x4(uint32_t& r0, uint32_t& r1,
                                            uint32_t& r2, uint32_t& r3,
                                            uint32_t addr) {
    asm volatile("ldmatrix.sync.aligned.m8n8.x4.shared.b16 {%0,%1,%2,%3}, [%4];"
                 : "=r"(r0), "=r"(r1), "=r"(r2), "=r"(r3) : "r"(addr));
}
__device__ __forceinline__ void ldmatrix_x2(uint32_t& r0, uint32_t& r1,
                                            uint32_t addr) {
    asm volatile("ldmatrix.sync.aligned.m8n8.x2.shared.b16 {%0,%1}, [%2];"
                 : "=r"(r0), "=r"(r1) : "r"(addr));
}
__device__ __forceinline__ void ldmatrix_x2_trans(uint32_t& r0, uint32_t& r1,
                                                  uint32_t addr) {
    asm volatile("ldmatrix.sync.aligned.m8n8.x2.trans.shared.b16 {%0,%1}, [%2];"
                 : "=r"(r0), "=r"(r1) : "r"(addr));
}
__device__ __forceinline__ void mma_bf16(float* d, const uint32_t* a,
                                         const uint32_t* b) {
    asm volatile(
        "mma.sync.aligned.m16n8k16.row.col.f32.bf16.bf16.f32 "
        "{%0,%1,%2,%3}, {%4,%5,%6,%7}, {%8,%9}, {%0,%1,%2,%3};"
        : "+f"(d[0]), "+f"(d[1]), "+f"(d[2]), "+f"(d[3])
        : "r"(a[0]), "r"(a[1]), "r"(a[2]), "r"(a[3]), "r"(b[0]), "r"(b[1]));
}
__device__ __forceinline__ void split_bf16(float v, __nv_bfloat16& h,
                                           __nv_bfloat16& l) {
    h = __float2bfloat16(v);
    l = __float2bfloat16(v - __bfloat162float(h));
}

// ---------------------------------------------------------------------------
// Split fp32 -> (hi, lo) bf16. sel=-1: src pointer (x); sel>=0: g_AO.
// ---------------------------------------------------------------------------
__global__ __launch_bounds__(256)
void split_kernel(const float* src, int sel)
{
    const float* A = (sel >= 0) ? g_AO : src;
    size_t i4 = ((size_t)blockIdx.x * 256 + threadIdx.x) * 4;
    float4 v = *(const float4*)&A[i4];
    float vs[4] = {v.x, v.y, v.z, v.w};
    __nv_bfloat16 h[4], l[4];
#pragma unroll
    for (int j = 0; j < 4; j++) split_bf16(vs[j], h[j], l[j]);
    __nv_bfloat162 h0 = {h[0], h[1]}, h1 = {h[2], h[3]};
    __nv_bfloat162 l0 = {l[0], l[1]}, l1 = {l[2], l[3]};
    uint2 uh, ul;
    uh.x = *(uint32_t*)&h0; uh.y = *(uint32_t*)&h1;
    ul.x = *(uint32_t*)&l0; ul.y = *(uint32_t*)&l1;
    *(uint2*)&g_xh[i4] = uh;
    *(uint2*)&g_xl[i4] = ul;
}

// ---------------------------------------------------------------------------
// W [K,N] fp32 -> transposed (hi, lo) bf16 [N,K]; slot = blockIdx.z.
// ---------------------------------------------------------------------------
__global__ __launch_bounds__(256)
void wsplit_kernel(const float* w0, const float* w1, const float* w2)
{
    __shared__ float ts[32][33];
    const int z = blockIdx.z;
    const float* W = (z == 0) ? w0 : (z == 1) ? w1 : w2;
    __nv_bfloat16* dh = g_wh + (size_t)z * D2;
    __nv_bfloat16* dl = g_wl + (size_t)z * D2;
    const int tx = threadIdx.x & 31, ty = threadIdx.x >> 5;
    const int n0 = blockIdx.x * 32, k0 = blockIdx.y * 32;
#pragma unroll
    for (int i = 0; i < 4; i++)
        ts[ty + i * 8][tx] = W[(size_t)(k0 + ty + i * 8) * D_MODEL + n0 + tx];
    __syncthreads();
#pragma unroll
    for (int i = 0; i < 4; i++) {
        float a = ts[tx][ty + i * 8];
        __nv_bfloat16 h, l;
        split_bf16(a, h, l);
        size_t o = (size_t)(n0 + ty + i * 8) * D_MODEL + k0 + tx;
        dh[o] = h; dl[o] = l;
    }
}

// ---------------------------------------------------------------------------
// HMMA bf16x3 GEMM (unchanged proven config).
// ---------------------------------------------------------------------------
#define KC 32
#define NCHUNK (D_MODEL / KC)
#define SSTRIDE 40

__global__ __launch_bounds__(256)
void tc_gemm_kernel(const float* __restrict__ b0, const float* __restrict__ b1,
                    const float* __restrict__ b2, float* C, int qkvMode)
{
    __shared__ __nv_bfloat16 sAh[128][SSTRIDE];
    __shared__ __nv_bfloat16 sAl[128][SSTRIDE];
    __shared__ __nv_bfloat16 sBh[128][SSTRIDE];
    __shared__ __nv_bfloat16 sBl[128][SSTRIDE];

    const int z = qkvMode ? blockIdx.z : 0;
    const float* bias = (z == 0) ? b0 : (z == 1) ? b1 : b2;
    const __nv_bfloat16* wh = g_wh + (size_t)z * D2;
    const __nv_bfloat16* wl = g_wl + (size_t)z * D2;

    const int tid  = threadIdx.x;
    const int wid  = tid >> 5;
    const int lane = tid & 31;
    const int wm   = (wid & 1) * 64;
    const int wn   = (wid >> 1) * 32;

    const int bn = blockIdx.x * 128;
    const int bm = blockIdx.y * 128;

    float acc[4][4][4];
#pragma unroll
    for (int i = 0; i < 4; i++)
#pragma unroll
        for (int j = 0; j < 4; j++)
#pragma unroll
            for (int t = 0; t < 4; t++) acc[i][j][t] = 0.f;

    const int ldRow = tid >> 2;
    const int ldSeg = tid & 3;

    const uint32_t aAh = smem_u32(sAh), aAl = smem_u32(sAl);
    const uint32_t aBh = smem_u32(sBh), aBl = smem_u32(sBl);
    const int aRow = wm + (lane & 15);
    const int aKh  = (lane >> 4);
    const int bRow = wn + (lane & 7);
    const int bKh  = (lane >> 3) & 1;

    for (int c = 0; c < NCHUNK; c++) {
        const int k0 = c * KC;
        __syncthreads();
#pragma unroll
        for (int u = 0; u < 2; u++) {
            const int r = ldRow + u * 64;
            const size_t gA = (size_t)(bm + r) * D_MODEL + k0 + ldSeg * 8;
            const size_t gB = (size_t)(bn + r) * D_MODEL + k0 + ldSeg * 8;
            *(uint4*)&sAh[r][ldSeg * 8] = *(const uint4*)&g_xh[gA];
            *(uint4*)&sAl[r][ldSeg * 8] = *(const uint4*)&g_xl[gA];
            *(uint4*)&sBh[r][ldSeg * 8] = *(const uint4*)&wh[gB];
            *(uint4*)&sBl[r][ldSeg * 8] = *(const uint4*)&wl[gB];
        }
        __syncthreads();

#pragma unroll
        for (int step = 0; step < 2; step++) {
            const uint32_t kByteA = (uint32_t)(step * 32 + aKh * 16);
            const uint32_t kByteB = (uint32_t)(step * 32 + bKh * 16);

            uint32_t Bh[4][2], Bl[4][2];
#pragma unroll
            for (int nt = 0; nt < 4; nt++) {
                uint32_t off = (uint32_t)(bRow + nt * 8) * (SSTRIDE * 2) + kByteB;
                ldmatrix_x2(Bh[nt][0], Bh[nt][1], aBh + off);
                ldmatrix_x2(Bl[nt][0], Bl[nt][1], aBl + off);
            }
#pragma unroll
            for (int mt = 0; mt < 4; mt++) {
                uint32_t off = (uint32_t)(aRow + mt * 16) * (SSTRIDE * 2) + kByteA;
                uint32_t Ah[4], Al[4];
                ldmatrix_x4(Ah[0], Ah[1], Ah[2], Ah[3], aAh + off);
                ldmatrix_x4(Al[0], Al[1], Al[2], Al[3], aAl + off);
#pragma unroll
                for (int nt = 0; nt < 4; nt++) {
                    mma_bf16(acc[mt][nt], Ah, Bh[nt]);
                    mma_bf16(acc[mt][nt], Al, Bh[nt]);
                    mma_bf16(acc[mt][nt], Ah, Bl[nt]);
                }
            }
        }
    }

    __nv_bfloat16* dh = (z == 0) ? g_Qh : (z == 1) ? g_Kh : g_Vh;
    __nv_bfloat16* dl = (z == 0) ? g_Ql : (z == 1) ? g_Kl : g_Vl;

    const int cg = lane >> 2;
    const int ct = (lane & 3) * 2;
#pragma unroll
    for (int mt = 0; mt < 4; mt++) {
#pragma unroll
        for (int nt = 0; nt < 4; nt++) {
            const int col = bn + wn + nt * 8 + ct;
            const float2 bv = *(const float2*)&bias[col];
            const int r0 = bm + wm + mt * 16 + cg;
            float e[2][2] = {{acc[mt][nt][0] + bv.x, acc[mt][nt][1] + bv.y},
                             {acc[mt][nt][2] + bv.x, acc[mt][nt][3] + bv.y}};
            if (!qkvMode) {
                *(float2*)&C[(size_t)r0 * D_MODEL + col]       = *(float2*)e[0];
                *(float2*)&C[(size_t)(r0 + 8) * D_MODEL + col] = *(float2*)e[1];
            } else {
#pragma unroll
                for (int u = 0; u < 2; u++) {
                    __nv_bfloat16 h0, l0, h1, l1;
                    split_bf16(e[u][0], h0, l0);
                    split_bf16(e[u][1], h1, l1);
                    __nv_bfloat162 ph = {h0, h1}, pl = {l0, l1};
                    size_t o = (size_t)(r0 + u * 8) * D_MODEL + col;
                    *(__nv_bfloat162*)&dh[o] = ph;
                    *(__nv_bfloat162*)&dl[o] = pl;
                }
            }
        }
    }
}

// ---------------------------------------------------------------------------
// Attention phase 1: scores + online (m,l). 256 threads, 8 warps (2m x 4n),
// warp tile 32x32, CTA tile 64q x 128k. Dynamic smem (55.3 KB):
//   sQh/sQl [64][72], sKh/sKl [128][72]. Stride 72 = 144B rows (16B aligned).
// ---------------------------------------------------------------------------
#define ATS 72
#define SCORE_SMEM ((64 * ATS * 2 + 128 * ATS * 2) * 2)   // 55296 bytes
#define PV_SMEM    ((128 * ATS * 2 + 64 * ATS * 2) * 2)   // 55296 bytes

__global__ __launch_bounds__(256)
void attn_score_kernel(const int* __restrict__ mask, float* __restrict__ attnW)
{
    extern __shared__ char dynS[];
    __nv_bfloat16* sQh = (__nv_bfloat16*)dynS;
    __nv_bfloat16* sQl = sQh + 64 * ATS;
    __nv_bfloat16* sKh = sQl + 64 * ATS;
    __nv_bfloat16* sKl = sKh + 128 * ATS;
    __shared__ int   maskS[128];
    __shared__ float sM[4][64], sL[4][64];

    const int qt = blockIdx.x, h = blockIdx.y, b = blockIdx.z;
    const int tid  = threadIdx.x;
    const int wid  = tid >> 5;
    const int lane = tid & 31;
    const int wm   = (wid & 1) * 32;     // 2 m-groups
    const int wn   = (wid >> 1) * 32;    // 4 n-groups -> 128 k
    const int q0   = qt * 64;

    const uint32_t aQh = smem_u32(sQh), aQl = smem_u32(sQl);
    const uint32_t aKh = smem_u32(sKh), aKl = smem_u32(sKl);

    // stage Q once: 64 rows x 64 bf16, 256 threads -> 16 bf16 each
    {
        const int r = tid >> 2, c = (tid & 3) * 16;
        const size_t g = (size_t)(b * SEQ + q0 + r) * D_MODEL + h * HEAD_DIM + c;
        *(uint4*)&sQh[r * ATS + c]     = *(const uint4*)&g_Qh[g];
        *(uint4*)&sQh[r * ATS + c + 8] = *(const uint4*)&g_Qh[g + 8];
        *(uint4*)&sQl[r * ATS + c]     = *(const uint4*)&g_Ql[g];
        *(uint4*)&sQl[r * ATS + c + 8] = *(const uint4*)&g_Ql[g + 8];
    }

    const size_t rowBase = (size_t)(b * NUM_HEADS + h) * SEQ + q0;

    float rm[4], rl[4];
#pragma unroll
    for (int i = 0; i < 4; i++) { rm[i] = -3.0e38f; rl[i] = 0.f; }

    for (int ks = 0; ks < SEQ; ks += 128) {
        __syncthreads();
        // stage K: 128 rows x 64 bf16, 256 threads -> 32 bf16 each
        {
            const int r = tid >> 1, c = (tid & 1) * 32;
            const size_t g = (size_t)(b * SEQ + ks + r) * D_MODEL
                           + h * HEAD_DIM + c;
#pragma unroll
            for (int j = 0; j < 4; j++)
                *(uint4*)&sKh[r * ATS + c + j * 8] = *(const uint4*)&g_Kh[g + j * 8];
#pragma unroll
            for (int j = 0; j < 4; j++)
                *(uint4*)&sKl[r * ATS + c + j * 8] = *(const uint4*)&g_Kl[g + j * 8];
            if (tid < 128) maskS[tid] = mask[b * SEQ + ks + tid];
        }
        __syncthreads();

        float acc[2][4][4];
#pragma unroll
        for (int i = 0; i < 2; i++)
#pragma unroll
            for (int j = 0; j < 4; j++)
#pragma unroll
                for (int t = 0; t < 4; t++) acc[i][j][t] = 0.f;

        const uint32_t aRowOff = (uint32_t)(wm + (lane & 15)) * (ATS * 2);
        const uint32_t akh = (uint32_t)(lane >> 4) * 16;
        const uint32_t bRowOff = (uint32_t)(wn + (lane & 7)) * (ATS * 2);
        const uint32_t bkh = (uint32_t)((lane >> 3) & 1) * 16;
#pragma unroll
        for (int st = 0; st < 4; st++) {
            uint32_t Bh[4][2], Bl[4][2];
#pragma unroll
            for (int nt = 0; nt < 4; nt++) {
                uint32_t off = bRowOff + (uint32_t)(nt * 8) * (ATS * 2)
                             + (uint32_t)(st * 32) + bkh;
                ldmatrix_x2(Bh[nt][0], Bh[nt][1], aKh + off);
                ldmatrix_x2(Bl[nt][0], Bl[nt][1], aKl + off);
            }
#pragma unroll
            for (int mt = 0; mt < 2; mt++) {
                uint32_t off = aRowOff + (uint32_t)(mt * 16) * (ATS * 2)
                             + (uint32_t)(st * 32) + akh;
                uint32_t Ah[4], Al[4];
                ldmatrix_x4(Ah[0], Ah[1], Ah[2], Ah[3], aQh + off);
                ldmatrix_x4(Al[0], Al[1], Al[2], Al[3], aQl + off);
#pragma unroll
                for (int nt = 0; nt < 4; nt++) {
                    mma_bf16(acc[mt][nt], Ah, Bh[nt]);
                    mma_bf16(acc[mt][nt], Al, Bh[nt]);
                    mma_bf16(acc[mt][nt], Ah, Bl[nt]);
                }
            }
        }

        // scale + mask, write raw scores, update online (m,l)
        const int cg = lane >> 2, ct = (lane & 3) * 2;
#pragma unroll
        for (int mt = 0; mt < 2; mt++) {
#pragma unroll
            for (int u = 0; u < 2; u++) {
                const int idx = mt * 2 + u;
                const int rq = wm + mt * 16 + cg + u * 8;
                float v[8];
#pragma unroll
                for (int nt = 0; nt < 4; nt++) {
                    const int col = wn + nt * 8 + ct;
                    const bool m0 = (maskS[col] == 0), m1 = (maskS[col + 1] == 0);
                    float a0 = m0 ? -3.0e38f : acc[mt][nt][u * 2 + 0] * 0.125f;
                    float a1 = m1 ? -3.0e38f : acc[mt][nt][u * 2 + 1] * 0.125f;
                    v[nt * 2 + 0] = a0; v[nt * 2 + 1] = a1;
                    *(float2*)&attnW[(rowBase + rq) * SEQ + ks + col] =
                        make_float2(a0, a1);
                }
                float tm = v[0];
#pragma unroll
                for (int j = 1; j < 8; j++) tm = fmaxf(tm, v[j]);
                tm = fmaxf(tm, __shfl_xor_sync(0xffffffffu, tm, 1));
                tm = fmaxf(tm, __shfl_xor_sync(0xffffffffu, tm, 2));
                float nm = fmaxf(rm[idx], tm);
                float ps = 0.f;
#pragma unroll
                for (int j = 0; j < 8; j++) ps += __expf(v[j] - nm);
                ps += __shfl_xor_sync(0xffffffffu, ps, 1);
                ps += __shfl_xor_sync(0xffffffffu, ps, 2);
                rl[idx] = rl[idx] * __expf(rm[idx] - nm) + ps;
                rm[idx] = nm;
            }
        }
    }

    // combine over the 4 column groups
    const int g = wid >> 1;
    if ((lane & 3) == 0) {
        const int cg = lane >> 2;
#pragma unroll
        for (int mt = 0; mt < 2; mt++)
#pragma unroll
            for (int u = 0; u < 2; u++) {
                const int r = wm + mt * 16 + cg + u * 8;
                sM[g][r] = rm[mt * 2 + u];
                sL[g][r] = rl[mt * 2 + u];
            }
    }
    __syncthreads();
    if (tid < 64) {
        float M = sM[0][tid];
#pragma unroll
        for (int gg = 1; gg < 4; gg++) M = fmaxf(M, sM[gg][tid]);
        float L = 0.f;
#pragma unroll
        for (int gg = 0; gg < 4; gg++)
            L += sL[gg][tid] * __expf(sM[gg][tid] - M);
        g_m [rowBase + tid] = M;
        g_il[rowBase + tid] = 1.0f / L;
    }
}

// ---------------------------------------------------------------------------
// Attention phase 2: finalize P in place, O = P @ V. 256 threads, 8 warps
// (4m x 2n), warp tile 32x32, CTA tile 128q x 64d, k-tiles of 64.
// Dynamic smem: sPh/sPl [128][72], sVh/sVl [64][72].
// ---------------------------------------------------------------------------
__global__ __launch_bounds__(256)
void attn_pv_kernel(float* __restrict__ attnW)
{
    extern __shared__ char dynS[];
    __nv_bfloat16* sPh = (__nv_bfloat16*)dynS;
    __nv_bfloat16* sPl = sPh + 128 * ATS;
    __nv_bfloat16* sVh = sPl + 128 * ATS;
    __nv_bfloat16* sVl = sVh + 64 * ATS;

    const int qt = blockIdx.x, h = blockIdx.y, b = blockIdx.z;
    const int tid  = threadIdx.x;
    const int wid  = tid >> 5;
    const int lane = tid & 31;
    const int wm   = (wid & 3) * 32;     // 4 m-groups -> 128 q
    const int wn   = (wid >> 2) * 32;    // 2 n-groups -> 64 d
    const int q0   = qt * 128;

    const uint32_t aPh = smem_u32(sPh), aPl = smem_u32(sPl);
    const uint32_t aVh = smem_u32(sVh), aVl = smem_u32(sVl);

    const size_t rowBase = (size_t)(b * NUM_HEADS + h) * SEQ + q0;

    const int prow = tid >> 1, pcb = (tid & 1) * 32;   // P stage: 128r x 64c
    const float prM  = g_m [rowBase + prow];
    const float prIL = g_il[rowBase + prow];

    float acc[2][4][4];
#pragma unroll
    for (int i = 0; i < 2; i++)
#pragma unroll
        for (int j = 0; j < 4; j++)
#pragma unroll
            for (int t = 0; t < 4; t++) acc[i][j][t] = 0.f;

    for (int ks = 0; ks < SEQ; ks += 64) {
        __syncthreads();
        // P tile: 128 rows x 64 k-cols; raw fp32 -> exp*invl -> write back + smem
        {
            float* pr = attnW + (rowBase + prow) * SEQ + ks + pcb;
#pragma unroll
            for (int g = 0; g < 8; g++) {
                float4 f = *(const float4*)&pr[g * 4];
                f.x = __expf(f.x - prM) * prIL;
                f.y = __expf(f.y - prM) * prIL;
                f.z = __expf(f.z - prM) * prIL;
                f.w = __expf(f.w - prM) * prIL;
                *(float4*)&pr[g * 4] = f;
                __nv_bfloat16 h0, l0, h1, l1, h2, l2, h3, l3;
                split_bf16(f.x, h0, l0); split_bf16(f.y, h1, l1);
                split_bf16(f.z, h2, l2); split_bf16(f.w, h3, l3);
                __nv_bfloat162 ha = {h0, h1}, hb = {h2, h3};
                __nv_bfloat162 la = {l0, l1}, lb = {l2, l3};
                uint2 uh, ul;
                uh.x = *(uint32_t*)&ha; uh.y = *(uint32_t*)&hb;
                ul.x = *(uint32_t*)&la; ul.y = *(uint32_t*)&lb;
                *(uint2*)&sPh[prow * ATS + pcb + g * 4] = uh;
                *(uint2*)&sPl[prow * ATS + pcb + g * 4] = ul;
            }
        }
        // V tile: 64 k-rows x 64 d; 256 threads -> 16 bf16 each
        {
            const int r = tid >> 2, c = (tid & 3) * 16;
            const size_t g = (size_t)(b * SEQ + ks + r) * D_MODEL
                           + h * HEAD_DIM + c;
            *(uint4*)&sVh[r * ATS + c]     = *(const uint4*)&g_Vh[g];
            *(uint4*)&sVh[r * ATS + c + 8] = *(const uint4*)&g_Vh[g + 8];
            *(uint4*)&sVl[r * ATS + c]     = *(const uint4*)&g_Vl[g];
            *(uint4*)&sVl[r * ATS + c + 8] = *(const uint4*)&g_Vl[g + 8];
        }
        __syncthreads();

        const uint32_t aRowOff = (uint32_t)(wm + (lane & 15)) * (ATS * 2);
        const uint32_t akh = (uint32_t)(lane >> 4) * 16;
#pragma unroll
        for (int st = 0; st < 4; st++) {
            uint32_t Bh[4][2], Bl[4][2];
#pragma unroll
            for (int nt = 0; nt < 4; nt++) {
                uint32_t off = (uint32_t)(st * 16 + (lane & 15)) * (ATS * 2)
                             + (uint32_t)(wn + nt * 8) * 2;
                ldmatrix_x2_trans(Bh[nt][0], Bh[nt][1], aVh + off);
                ldmatrix_x2_trans(Bl[nt][0], Bl[nt][1], aVl + off);
            }
#pragma unroll
            for (int mt = 0; mt < 2; mt++) {
                uint32_t off = aRowOff + (uint32_t)(mt * 16) * (ATS * 2)
                             + (uint32_t)(st * 32) + akh;
                uint32_t Ah[4], Al[4];
                ldmatrix_x4(Ah[0], Ah[1], Ah[2], Ah[3], aPh + off);
                ldmatrix_x4(Al[0], Al[1], Al[2], Al[3], aPl + off);
#pragma unroll
                for (int nt = 0; nt < 4; nt++) {
                    mma_bf16(acc[mt][nt], Ah, Bh[nt]);
                    mma_bf16(acc[mt][nt], Al, Bh[nt]);
                    mma_bf16(acc[mt][nt], Ah, Bl[nt]);
                }
            }
        }
    }

    const int cg = lane >> 2, ct = (lane & 3) * 2;
#pragma unroll
    for (int mt = 0; mt < 2; mt++) {
#pragma unroll
        for (int nt = 0; nt < 4; nt++) {
            const int cd = wn + nt * 8 + ct;
#pragma unroll
            for (int u = 0; u < 2; u++) {
                const int rq = q0 + wm + mt * 16 + cg + u * 8;
                float2 v = {acc[mt][nt][u * 2 + 0], acc[mt][nt][u * 2 + 1]};
                *(float2*)&g_AO[(size_t)(b * SEQ + rq) * D_MODEL
                                + h * HEAD_DIM + cd] = v;
            }
        }
    }
}

// ---------------------------------------------------------------------------
// Launch
// ---------------------------------------------------------------------------
extern "C" void kernel_launch(void* const* d_in, const int* in_sizes, int n_in,
                              void* d_out, int out_size)
{
    const float* x  = (const float*)d_in[0];
    const int*   am = (const int*)  d_in[1];
    const float* Wq = (const float*)d_in[2];
    const float* bq = (const float*)d_in[3];
    const float* Wk = (const float*)d_in[4];
    const float* bk = (const float*)d_in[5];
    const float* Wv = (const float*)d_in[6];
    const float* bv = (const float*)d_in[7];
    const float* Wo = (const float*)d_in[8];
    const float* bo = (const float*)d_in[9];

    float* out   = (float*)d_out;
    float* attnW = out + (size_t)NROWS * D_MODEL;

    cudaFuncSetAttribute((const void*)attn_score_kernel,
                         cudaFuncAttributeMaxDynamicSharedMemorySize, SCORE_SMEM);
    cudaFuncSetAttribute((const void*)attn_pv_kernel,
                         cudaFuncAttributeMaxDynamicSharedMemorySize, PV_SMEM);

    const int splitBlocks = (NROWS * D_MODEL) / (256 * 4);

    split_kernel<<<splitBlocks, 256>>>(x, -1);

    dim3 gW3(D_MODEL / 32, D_MODEL / 32, 3);
    wsplit_kernel<<<gW3, 256>>>(Wq, Wk, Wv);
    dim3 gG3(D_MODEL / 128, NROWS / 128, 3);
    tc_gemm_kernel<<<gG3, 256>>>(bq, bk, bv, nullptr, 1);

    dim3 gScore(SEQ / 64, NUM_HEADS, BATCH);    // (32, 16, 2)
    attn_score_kernel<<<gScore, 256, SCORE_SMEM>>>(am, attnW);
    dim3 gPv(SEQ / 128, NUM_HEADS, BATCH);      // (16, 16, 2)
    attn_pv_kernel<<<gPv, 256, PV_SMEM>>>(attnW);

    split_kernel<<<splitBlocks, 256>>>(nullptr, 3);
    dim3 gW1(D_MODEL / 32, D_MODEL / 32, 1);
    wsplit_kernel<<<gW1, 256>>>(Wo, Wo, Wo);
    dim3 gG1(D_MODEL / 128, NROWS / 128, 1);
    tc_gemm_kernel<<<gG1, 256>>>(bo, bo, bo, out, 0);
}

// round 16
// speedup vs baseline: 3.1755x; 3.1755x over previous
#include <cuda_runtime.h>
#include <cuda_bf16.h>
#include <cstdint>
#include <math.h>

#define D_MODEL   1024
#define NUM_HEADS 16
#define HEAD_DIM  64
#define BATCH     2
#define SEQ       2048
#define NROWS     (BATCH * SEQ)   // 4096
#define D2        ((size_t)D_MODEL * D_MODEL)

// ---------------------------------------------------------------------------
// Scratch (device globals; no runtime allocation allowed)
// ---------------------------------------------------------------------------
__device__ float g_AO[(size_t)NROWS * D_MODEL];
__device__ __nv_bfloat16 g_xh[(size_t)NROWS * D_MODEL];
__device__ __nv_bfloat16 g_xl[(size_t)NROWS * D_MODEL];
__device__ __nv_bfloat16 g_wh[3 * D2];
__device__ __nv_bfloat16 g_wl[3 * D2];
__device__ __nv_bfloat16 g_Qh[(size_t)NROWS * D_MODEL];
__device__ __nv_bfloat16 g_Ql[(size_t)NROWS * D_MODEL];
__device__ __nv_bfloat16 g_Kh[(size_t)NROWS * D_MODEL];
__device__ __nv_bfloat16 g_Kl[(size_t)NROWS * D_MODEL];
__device__ __nv_bfloat16 g_Vh[(size_t)NROWS * D_MODEL];
__device__ __nv_bfloat16 g_Vl[(size_t)NROWS * D_MODEL];
__device__ float g_m [(size_t)BATCH * NUM_HEADS * SEQ];
__device__ float g_il[(size_t)BATCH * NUM_HEADS * SEQ];

// ---------------------------------------------------------------------------
// HMMA helpers (mma.sync bf16, base sm_103 target)
// ---------------------------------------------------------------------------
__device__ __forceinline__ uint32_t smem_u32(const void* p) {
    uint32_t a;
    asm("{ .reg .u64 t; cvta.to.shared.u64 t, %1; cvt.u32.u64 %0, t; }"
        : "=r"(a) : "l"(p));
    return a;
}
__device__ __forceinline__ void ldmatrix_x4(uint32_t& r0, uint32_t& r1,
                                            uint32_t& r2, uint32_t& r3,
                                            uint32_t addr) {
    asm volatile("ldmatrix.sync.aligned.m8n8.x4.shared.b16 {%0,%1,%2,%3}, [%4];"
                 : "=r"(r0), "=r"(r1), "=r"(r2), "=r"(r3) : "r"(addr));
}
__device__ __forceinline__ void ldmatrix_x2(uint32_t& r0, uint32_t& r1,
                                            uint32_t addr) {
    asm volatile("ldmatrix.sync.aligned.m8n8.x2.shared.b16 {%0,%1}, [%2];"
                 : "=r"(r0), "=r"(r1) : "r"(addr));
}
__device__ __forceinline__ void ldmatrix_x2_trans(uint32_t& r0, uint32_t& r1,
                                                  uint32_t addr) {
    asm volatile("ldmatrix.sync.aligned.m8n8.x2.trans.shared.b16 {%0,%1}, [%2];"
                 : "=r"(r0), "=r"(r1) : "r"(addr));
}
__device__ __forceinline__ void mma_bf16(float* d, const uint32_t* a,
                                         const uint32_t* b) {
    asm volatile(
        "mma.sync.aligned.m16n8k16.row.col.f32.bf16.bf16.f32 "
        "{%0,%1,%2,%3}, {%4,%5,%6,%7}, {%8,%9}, {%0,%1,%2,%3};"
        : "+f"(d[0]), "+f"(d[1]), "+f"(d[2]), "+f"(d[3])
        : "r"(a[0]), "r"(a[1]), "r"(a[2]), "r"(a[3]), "r"(b[0]), "r"(b[1]));
}
__device__ __forceinline__ void split_bf16(float v, __nv_bfloat16& h,
                                           __nv_bfloat16& l) {
    h = __float2bfloat16(v);
    l = __float2bfloat16(v - __bfloat162float(h));
}

// ---------------------------------------------------------------------------
// Split fp32 -> (hi, lo) bf16. sel=-1: src pointer (x); sel>=0: g_AO.
// ---------------------------------------------------------------------------
__global__ __launch_bounds__(256)
void split_kernel(const float* src, int sel)
{
    const float* A = (sel >= 0) ? g_AO : src;
    size_t i4 = ((size_t)blockIdx.x * 256 + threadIdx.x) * 4;
    float4 v = *(const float4*)&A[i4];
    float vs[4] = {v.x, v.y, v.z, v.w};
    __nv_bfloat16 h[4], l[4];
#pragma unroll
    for (int j = 0; j < 4; j++) split_bf16(vs[j], h[j], l[j]);
    __nv_bfloat162 h0 = {h[0], h[1]}, h1 = {h[2], h[3]};
    __nv_bfloat162 l0 = {l[0], l[1]}, l1 = {l[2], l[3]};
    uint2 uh, ul;
    uh.x = *(uint32_t*)&h0; uh.y = *(uint32_t*)&h1;
    ul.x = *(uint32_t*)&l0; ul.y = *(uint32_t*)&l1;
    *(uint2*)&g_xh[i4] = uh;
    *(uint2*)&g_xl[i4] = ul;
}

// ---------------------------------------------------------------------------
// W [K,N] fp32 -> transposed (hi, lo) bf16 [N,K]; slot = blockIdx.z.
// ---------------------------------------------------------------------------
__global__ __launch_bounds__(256)
void wsplit_kernel(const float* w0, const float* w1, const float* w2)
{
    __shared__ float ts[32][33];
    const int z = blockIdx.z;
    const float* W = (z == 0) ? w0 : (z == 1) ? w1 : w2;
    __nv_bfloat16* dh = g_wh + (size_t)z * D2;
    __nv_bfloat16* dl = g_wl + (size_t)z * D2;
    const int tx = threadIdx.x & 31, ty = threadIdx.x >> 5;
    const int n0 = blockIdx.x * 32, k0 = blockIdx.y * 32;
#pragma unroll
    for (int i = 0; i < 4; i++)
        ts[ty + i * 8][tx] = W[(size_t)(k0 + ty + i * 8) * D_MODEL + n0 + tx];
    __syncthreads();
#pragma unroll
    for (int i = 0; i < 4; i++) {
        float a = ts[tx][ty + i * 8];
        __nv_bfloat16 h, l;
        split_bf16(a, h, l);
        size_t o = (size_t)(n0 + ty + i * 8) * D_MODEL + k0 + tx;
        dh[o] = h; dl[o] = l;
    }
}

// ---------------------------------------------------------------------------
// HMMA bf16x3 GEMM (unchanged proven config).
// ---------------------------------------------------------------------------
#define KC 32
#define NCHUNK (D_MODEL / KC)
#define SSTRIDE 40

__global__ __launch_bounds__(256)
void tc_gemm_kernel(const float* __restrict__ b0, const float* __restrict__ b1,
                    const float* __restrict__ b2, float* C, int qkvMode)
{
    __shared__ __nv_bfloat16 sAh[128][SSTRIDE];
    __shared__ __nv_bfloat16 sAl[128][SSTRIDE];
    __shared__ __nv_bfloat16 sBh[128][SSTRIDE];
    __shared__ __nv_bfloat16 sBl[128][SSTRIDE];

    const int z = qkvMode ? blockIdx.z : 0;
    const float* bias = (z == 0) ? b0 : (z == 1) ? b1 : b2;
    const __nv_bfloat16* wh = g_wh + (size_t)z * D2;
    const __nv_bfloat16* wl = g_wl + (size_t)z * D2;

    const int tid  = threadIdx.x;
    const int wid  = tid >> 5;
    const int lane = tid & 31;
    const int wm   = (wid & 1) * 64;
    const int wn   = (wid >> 1) * 32;

    const int bn = blockIdx.x * 128;
    const int bm = blockIdx.y * 128;

    float acc[4][4][4];
#pragma unroll
    for (int i = 0; i < 4; i++)
#pragma unroll
        for (int j = 0; j < 4; j++)
#pragma unroll
            for (int t = 0; t < 4; t++) acc[i][j][t] = 0.f;

    const int ldRow = tid >> 2;
    const int ldSeg = tid & 3;

    const uint32_t aAh = smem_u32(sAh), aAl = smem_u32(sAl);
    const uint32_t aBh = smem_u32(sBh), aBl = smem_u32(sBl);
    const int aRow = wm + (lane & 15);
    const int aKh  = (lane >> 4);
    const int bRow = wn + (lane & 7);
    const int bKh  = (lane >> 3) & 1;

    for (int c = 0; c < NCHUNK; c++) {
        const int k0 = c * KC;
        __syncthreads();
#pragma unroll
        for (int u = 0; u < 2; u++) {
            const int r = ldRow + u * 64;
            const size_t gA = (size_t)(bm + r) * D_MODEL + k0 + ldSeg * 8;
            const size_t gB = (size_t)(bn + r) * D_MODEL + k0 + ldSeg * 8;
            *(uint4*)&sAh[r][ldSeg * 8] = *(const uint4*)&g_xh[gA];
            *(uint4*)&sAl[r][ldSeg * 8] = *(const uint4*)&g_xl[gA];
            *(uint4*)&sBh[r][ldSeg * 8] = *(const uint4*)&wh[gB];
            *(uint4*)&sBl[r][ldSeg * 8] = *(const uint4*)&wl[gB];
        }
        __syncthreads();

#pragma unroll
        for (int step = 0; step < 2; step++) {
            const uint32_t kByteA = (uint32_t)(step * 32 + aKh * 16);
            const uint32_t kByteB = (uint32_t)(step * 32 + bKh * 16);

            uint32_t Bh[4][2], Bl[4][2];
#pragma unroll
            for (int nt = 0; nt < 4; nt++) {
                uint32_t off = (uint32_t)(bRow + nt * 8) * (SSTRIDE * 2) + kByteB;
                ldmatrix_x2(Bh[nt][0], Bh[nt][1], aBh + off);
                ldmatrix_x2(Bl[nt][0], Bl[nt][1], aBl + off);
            }
#pragma unroll
            for (int mt = 0; mt < 4; mt++) {
                uint32_t off = (uint32_t)(aRow + mt * 16) * (SSTRIDE * 2) + kByteA;
                uint32_t Ah[4], Al[4];
                ldmatrix_x4(Ah[0], Ah[1], Ah[2], Ah[3], aAh + off);
                ldmatrix_x4(Al[0], Al[1], Al[2], Al[3], aAl + off);
#pragma unroll
                for (int nt = 0; nt < 4; nt++) {
                    mma_bf16(acc[mt][nt], Ah, Bh[nt]);
                    mma_bf16(acc[mt][nt], Al, Bh[nt]);
                    mma_bf16(acc[mt][nt], Ah, Bl[nt]);
                }
            }
        }
    }

    __nv_bfloat16* dh = (z == 0) ? g_Qh : (z == 1) ? g_Kh : g_Vh;
    __nv_bfloat16* dl = (z == 0) ? g_Ql : (z == 1) ? g_Kl : g_Vl;

    const int cg = lane >> 2;
    const int ct = (lane & 3) * 2;
#pragma unroll
    for (int mt = 0; mt < 4; mt++) {
#pragma unroll
        for (int nt = 0; nt < 4; nt++) {
            const int col = bn + wn + nt * 8 + ct;
            const float2 bv = *(const float2*)&bias[col];
            const int r0 = bm + wm + mt * 16 + cg;
            float e[2][2] = {{acc[mt][nt][0] + bv.x, acc[mt][nt][1] + bv.y},
                             {acc[mt][nt][2] + bv.x, acc[mt][nt][3] + bv.y}};
            if (!qkvMode) {
                *(float2*)&C[(size_t)r0 * D_MODEL + col]       = *(float2*)e[0];
                *(float2*)&C[(size_t)(r0 + 8) * D_MODEL + col] = *(float2*)e[1];
            } else {
#pragma unroll
                for (int u = 0; u < 2; u++) {
                    __nv_bfloat16 h0, l0, h1, l1;
                    split_bf16(e[u][0], h0, l0);
                    split_bf16(e[u][1], h1, l1);
                    __nv_bfloat162 ph = {h0, h1}, pl = {l0, l1};
                    size_t o = (size_t)(r0 + u * 8) * D_MODEL + col;
                    *(__nv_bfloat162*)&dh[o] = ph;
                    *(__nv_bfloat162*)&dl[o] = pl;
                }
            }
        }
    }
}

// ---------------------------------------------------------------------------
// Attention pass 1 (stats only): R12 score kernel with the raw-score gmem
// writes REMOVED. Computes exact online (m, 1/l) per row -> g_m / g_il.
// 256 threads, 8 warps (2m x 4n), warp tile 32x16, 64q x 64k tiles.
// ---------------------------------------------------------------------------
#define ATS 72

__global__ __launch_bounds__(256)
void attn_stats_kernel(const int* __restrict__ mask)
{
    __shared__ __nv_bfloat16 sQh[64][ATS], sQl[64][ATS];
    __shared__ __nv_bfloat16 sKh[64][ATS], sKl[64][ATS];
    __shared__ int   maskS[64];
    __shared__ float sM[4][64], sL[4][64];

    const int qt = blockIdx.x, h = blockIdx.y, b = blockIdx.z;
    const int tid  = threadIdx.x;
    const int wid  = tid >> 5;
    const int lane = tid & 31;
    const int wm   = (wid & 1) * 32;
    const int wn   = (wid >> 1) * 16;
    const int q0   = qt * 64;

    const uint32_t aQh = smem_u32(sQh), aQl = smem_u32(sQl);
    const uint32_t aKh = smem_u32(sKh), aKl = smem_u32(sKl);

    {
        const int r = tid >> 2, s8 = (tid & 3) * 8;
        const size_t g = (size_t)(b * SEQ + q0 + r) * D_MODEL + h * HEAD_DIM;
        *(uint4*)&sQh[r][s8]      = *(const uint4*)&g_Qh[g + s8];
        *(uint4*)&sQh[r][s8 + 32] = *(const uint4*)&g_Qh[g + s8 + 32];
        *(uint4*)&sQl[r][s8]      = *(const uint4*)&g_Ql[g + s8];
        *(uint4*)&sQl[r][s8 + 32] = *(const uint4*)&g_Ql[g + s8 + 32];
    }

    const size_t rowBase = (size_t)(b * NUM_HEADS + h) * SEQ + q0;

    float rm[4], rl[4];
#pragma unroll
    for (int i = 0; i < 4; i++) { rm[i] = -3.0e38f; rl[i] = 0.f; }

    for (int ks = 0; ks < SEQ; ks += 64) {
        __syncthreads();
        {
            const int r = tid >> 2, s8 = (tid & 3) * 8;
            const size_t g = (size_t)(b * SEQ + ks + r) * D_MODEL + h * HEAD_DIM;
            *(uint4*)&sKh[r][s8]      = *(const uint4*)&g_Kh[g + s8];
            *(uint4*)&sKh[r][s8 + 32] = *(const uint4*)&g_Kh[g + s8 + 32];
            *(uint4*)&sKl[r][s8]      = *(const uint4*)&g_Kl[g + s8];
            *(uint4*)&sKl[r][s8 + 32] = *(const uint4*)&g_Kl[g + s8 + 32];
            if (tid < 64) maskS[tid] = mask[b * SEQ + ks + tid];
        }
        __syncthreads();

        float acc[2][2][4];
#pragma unroll
        for (int i = 0; i < 2; i++)
#pragma unroll
            for (int j = 0; j < 2; j++)
#pragma unroll
                for (int t = 0; t < 4; t++) acc[i][j][t] = 0.f;

#pragma unroll
        for (int st = 0; st < 4; st++) {
            const uint32_t kbA = (uint32_t)(st * 32 + (lane >> 4) * 16);
            const uint32_t kbB = (uint32_t)(st * 32 + ((lane >> 3) & 1) * 16);
            uint32_t Bh[2][2], Bl[2][2];
#pragma unroll
            for (int nt = 0; nt < 2; nt++) {
                uint32_t off = (uint32_t)(wn + nt * 8 + (lane & 7)) * (ATS * 2) + kbB;
                ldmatrix_x2(Bh[nt][0], Bh[nt][1], aKh + off);
                ldmatrix_x2(Bl[nt][0], Bl[nt][1], aKl + off);
            }
#pragma unroll
            for (int mt = 0; mt < 2; mt++) {
                uint32_t off = (uint32_t)(wm + mt * 16 + (lane & 15)) * (ATS * 2) + kbA;
                uint32_t Ah[4], Al[4];
                ldmatrix_x4(Ah[0], Ah[1], Ah[2], Ah[3], aQh + off);
                ldmatrix_x4(Al[0], Al[1], Al[2], Al[3], aQl + off);
#pragma unroll
                for (int nt = 0; nt < 2; nt++) {
                    mma_bf16(acc[mt][nt], Ah, Bh[nt]);
                    mma_bf16(acc[mt][nt], Al, Bh[nt]);
                    mma_bf16(acc[mt][nt], Ah, Bl[nt]);
                }
            }
        }

        const int cg = lane >> 2, ct = (lane & 3) * 2;
#pragma unroll
        for (int mt = 0; mt < 2; mt++) {
#pragma unroll
            for (int u = 0; u < 2; u++) {
                const int idx = mt * 2 + u;
                float v[4];
#pragma unroll
                for (int nt = 0; nt < 2; nt++) {
                    const int col = wn + nt * 8 + ct;
                    const bool m0 = (maskS[col] == 0), m1 = (maskS[col + 1] == 0);
                    v[nt * 2 + 0] = m0 ? -3.0e38f : acc[mt][nt][u * 2 + 0] * 0.125f;
                    v[nt * 2 + 1] = m1 ? -3.0e38f : acc[mt][nt][u * 2 + 1] * 0.125f;
                }
                float tm = fmaxf(fmaxf(v[0], v[1]), fmaxf(v[2], v[3]));
                tm = fmaxf(tm, __shfl_xor_sync(0xffffffffu, tm, 1));
                tm = fmaxf(tm, __shfl_xor_sync(0xffffffffu, tm, 2));
                float nm = fmaxf(rm[idx], tm);
                float ps = __expf(v[0] - nm) + __expf(v[1] - nm)
                         + __expf(v[2] - nm) + __expf(v[3] - nm);
                ps += __shfl_xor_sync(0xffffffffu, ps, 1);
                ps += __shfl_xor_sync(0xffffffffu, ps, 2);
                rl[idx] = rl[idx] * __expf(rm[idx] - nm) + ps;
                rm[idx] = nm;
            }
        }
    }

    const int g = wid >> 1;
    if ((lane & 3) == 0) {
        const int cg = lane >> 2;
#pragma unroll
        for (int mt = 0; mt < 2; mt++)
#pragma unroll
            for (int u = 0; u < 2; u++) {
                const int r = wm + mt * 16 + cg + u * 8;
                sM[g][r] = rm[mt * 2 + u];
                sL[g][r] = rl[mt * 2 + u];
            }
    }
    __syncthreads();
    if (tid < 64) {
        float M = sM[0][tid];
#pragma unroll
        for (int gg = 1; gg < 4; gg++) M = fmaxf(M, sM[gg][tid]);
        float L = 0.f;
#pragma unroll
        for (int gg = 0; gg < 4; gg++)
            L += sL[gg][tid] * __expf(sM[gg][tid] - M);
        g_m [rowBase + tid] = M;
        g_il[rowBase + tid] = 1.0f / L;
    }
}

// ---------------------------------------------------------------------------
// Attention pass 2: recompute S (same MMA sequence as stats -> bitwise-
// identical fp32), P = exp(S-m)*il in registers, write final P fp32 to attnW
// (the mandatory output), stage Ph/Pl in smem, accumulate O = P @ V -> g_AO.
// 256 threads, 8 warps. QK phase: rows (wid&1)*32, k-cols (wid>>1)*16.
// PV phase: rows (wid&1)*32, d-cols (wid>>1)*16 (R12-proven indices).
// Dynamic smem: 8 buffers [64][72] bf16 = 73728 B.
// ---------------------------------------------------------------------------
#define PVBUF (64 * ATS)
#define PV_SMEM (8 * PVBUF * 2)   // 73728 bytes

__global__ __launch_bounds__(256)
void attn_pv_kernel(const int* __restrict__ mask, float* __restrict__ attnW)
{
    extern __shared__ char dynS[];
    __nv_bfloat16* sQh = (__nv_bfloat16*)dynS;
    __nv_bfloat16* sQl = sQh + PVBUF;
    __nv_bfloat16* sKh = sQl + PVBUF;
    __nv_bfloat16* sKl = sKh + PVBUF;
    __nv_bfloat16* sVh = sKl + PVBUF;
    __nv_bfloat16* sVl = sVh + PVBUF;
    __nv_bfloat16* sPh = sVl + PVBUF;
    __nv_bfloat16* sPl = sPh + PVBUF;
    __shared__ int maskS[64];

    const int qt = blockIdx.x, h = blockIdx.y, b = blockIdx.z;
    const int tid  = threadIdx.x;
    const int wid  = tid >> 5;
    const int lane = tid & 31;
    const int wm   = (wid & 1) * 32;     // q-rows (QK and PV)
    const int wk   = (wid >> 1) * 16;    // QK k-col chunk
    const int wd   = (wid >> 1) * 16;    // PV d chunk
    const int q0   = qt * 64;

    const uint32_t aQh = smem_u32(sQh), aQl = smem_u32(sQl);
    const uint32_t aKh = smem_u32(sKh), aKl = smem_u32(sKl);
    const uint32_t aVh = smem_u32(sVh), aVl = smem_u32(sVl);
    const uint32_t aPh = smem_u32(sPh), aPl = smem_u32(sPl);

    const size_t rowBase = (size_t)(b * NUM_HEADS + h) * SEQ + q0;

    // stage Q once (64 rows x 64 bf16 per buffer)
    {
        const int r = tid >> 2, c = (tid & 3) * 16;
        const size_t g = (size_t)(b * SEQ + q0 + r) * D_MODEL + h * HEAD_DIM + c;
        *(uint4*)&sQh[r * ATS + c]     = *(const uint4*)&g_Qh[g];
        *(uint4*)&sQh[r * ATS + c + 8] = *(const uint4*)&g_Qh[g + 8];
        *(uint4*)&sQl[r * ATS + c]     = *(const uint4*)&g_Ql[g];
        *(uint4*)&sQl[r * ATS + c + 8] = *(const uint4*)&g_Ql[g + 8];
    }

    const int cg = lane >> 2, ct = (lane & 3) * 2;

    // per-lane row stats (loop-invariant)
    float pm[4], pil[4];
#pragma unroll
    for (int mt = 0; mt < 2; mt++)
#pragma unroll
        for (int u = 0; u < 2; u++) {
            const int r = wm + mt * 16 + cg + u * 8;
            pm [mt * 2 + u] = g_m [rowBase + r];
            pil[mt * 2 + u] = g_il[rowBase + r];
        }

    float pvacc[2][2][4];
#pragma unroll
    for (int i = 0; i < 2; i++)
#pragma unroll
        for (int j = 0; j < 2; j++)
#pragma unroll
            for (int t = 0; t < 4; t++) pvacc[i][j][t] = 0.f;

    for (int ks = 0; ks < SEQ; ks += 64) {
        __syncthreads();   // prev PV reads done before overwriting K/V
        {
            const int r = tid >> 2, c = (tid & 3) * 16;
            const size_t gk = (size_t)(b * SEQ + ks + r) * D_MODEL + h * HEAD_DIM + c;
            *(uint4*)&sKh[r * ATS + c]     = *(const uint4*)&g_Kh[gk];
            *(uint4*)&sKh[r * ATS + c + 8] = *(const uint4*)&g_Kh[gk + 8];
            *(uint4*)&sKl[r * ATS + c]     = *(const uint4*)&g_Kl[gk];
            *(uint4*)&sKl[r * ATS + c + 8] = *(const uint4*)&g_Kl[gk + 8];
            *(uint4*)&sVh[r * ATS + c]     = *(const uint4*)&g_Vh[gk];
            *(uint4*)&sVh[r * ATS + c + 8] = *(const uint4*)&g_Vh[gk + 8];
            *(uint4*)&sVl[r * ATS + c]     = *(const uint4*)&g_Vl[gk];
            *(uint4*)&sVl[r * ATS + c + 8] = *(const uint4*)&g_Vl[gk + 8];
            if (tid < 64) maskS[tid] = mask[b * SEQ + ks + tid];
        }
        __syncthreads();

        // ---- QK recompute: identical sequence to stats kernel ----
        float sacc[2][2][4];
#pragma unroll
        for (int i = 0; i < 2; i++)
#pragma unroll
            for (int j = 0; j < 2; j++)
#pragma unroll
                for (int t = 0; t < 4; t++) sacc[i][j][t] = 0.f;

#pragma unroll
        for (int st = 0; st < 4; st++) {
            const uint32_t kbA = (uint32_t)(st * 32 + (lane >> 4) * 16);
            const uint32_t kbB = (uint32_t)(st * 32 + ((lane >> 3) & 1) * 16);
            uint32_t Bh[2][2], Bl[2][2];
#pragma unroll
            for (int nt = 0; nt < 2; nt++) {
                uint32_t off = (uint32_t)(wk + nt * 8 + (lane & 7)) * (ATS * 2) + kbB;
                ldmatrix_x2(Bh[nt][0], Bh[nt][1], aKh + off);
                ldmatrix_x2(Bl[nt][0], Bl[nt][1], aKl + off);
            }
#pragma unroll
            for (int mt = 0; mt < 2; mt++) {
                uint32_t off = (uint32_t)(wm + mt * 16 + (lane & 15)) * (ATS * 2) + kbA;
                uint32_t Ah[4], Al[4];
                ldmatrix_x4(Ah[0], Ah[1], Ah[2], Ah[3], aQh + off);
                ldmatrix_x4(Al[0], Al[1], Al[2], Al[3], aQl + off);
#pragma unroll
                for (int nt = 0; nt < 2; nt++) {
                    mma_bf16(sacc[mt][nt], Ah, Bh[nt]);
                    mma_bf16(sacc[mt][nt], Al, Bh[nt]);
                    mma_bf16(sacc[mt][nt], Ah, Bl[nt]);
                }
            }
        }

        // ---- P finalize: write fp32 output + stage bf16 hi/lo ----
#pragma unroll
        for (int mt = 0; mt < 2; mt++) {
#pragma unroll
            for (int nt = 0; nt < 2; nt++) {
                const int col = wk + nt * 8 + ct;
                const bool m0 = (maskS[col] == 0), m1 = (maskS[col + 1] == 0);
#pragma unroll
                for (int u = 0; u < 2; u++) {
                    const int idx = mt * 2 + u;
                    const int rq  = wm + mt * 16 + cg + u * 8;
                    float p0 = m0 ? 0.f
                        : __expf(sacc[mt][nt][u * 2 + 0] * 0.125f - pm[idx]) * pil[idx];
                    float p1 = m1 ? 0.f
                        : __expf(sacc[mt][nt][u * 2 + 1] * 0.125f - pm[idx]) * pil[idx];
                    *(float2*)&attnW[(rowBase + rq) * SEQ + ks + col] =
                        make_float2(p0, p1);
                    __nv_bfloat16 h0, l0, h1, l1;
                    split_bf16(p0, h0, l0);
                    split_bf16(p1, h1, l1);
                    __nv_bfloat162 ph = {h0, h1}, pl = {l0, l1};
                    *(__nv_bfloat162*)&sPh[rq * ATS + col] = ph;
                    *(__nv_bfloat162*)&sPl[rq * ATS + col] = pl;
                }
            }
        }
        __syncthreads();

        // ---- PV: R12-proven index patterns ----
        const uint32_t aRowOff = (uint32_t)(wm + (lane & 15)) * (ATS * 2);
        const uint32_t akh = (uint32_t)(lane >> 4) * 16;
#pragma unroll
        for (int st = 0; st < 4; st++) {
            uint32_t Bh[2][2], Bl[2][2];
#pragma unroll
            for (int nt = 0; nt < 2; nt++) {
                uint32_t off = (uint32_t)(st * 16 + (lane & 15)) * (ATS * 2)
                             + (uint32_t)(wd + nt * 8) * 2;
                ldmatrix_x2_trans(Bh[nt][0], Bh[nt][1], aVh + off);
                ldmatrix_x2_trans(Bl[nt][0], Bl[nt][1], aVl + off);
            }
#pragma unroll
            for (int mt = 0; mt < 2; mt++) {
                uint32_t off = aRowOff + (uint32_t)(mt * 16) * (ATS * 2)
                             + (uint32_t)(st * 32) + akh;
                uint32_t Ah[4], Al[4];
                ldmatrix_x4(Ah[0], Ah[1], Ah[2], Ah[3], aPh + off);
                ldmatrix_x4(Al[0], Al[1], Al[2], Al[3], aPl + off);
#pragma unroll
                for (int nt = 0; nt < 2; nt++) {
                    mma_bf16(pvacc[mt][nt], Ah, Bh[nt]);
                    mma_bf16(pvacc[mt][nt], Al, Bh[nt]);
                    mma_bf16(pvacc[mt][nt], Ah, Bl[nt]);
                }
            }
        }
    }

    // epilogue -> g_AO
#pragma unroll
    for (int mt = 0; mt < 2; mt++) {
#pragma unroll
        for (int nt = 0; nt < 2; nt++) {
            const int cd = wd + nt * 8 + ct;
#pragma unroll
            for (int u = 0; u < 2; u++) {
                const int rq = q0 + wm + mt * 16 + cg + u * 8;
                float2 v = {pvacc[mt][nt][u * 2 + 0], pvacc[mt][nt][u * 2 + 1]};
                *(float2*)&g_AO[(size_t)(b * SEQ + rq) * D_MODEL
                                + h * HEAD_DIM + cd] = v;
            }
        }
    }
}

// ---------------------------------------------------------------------------
// Launch
// ---------------------------------------------------------------------------
extern "C" void kernel_launch(void* const* d_in, const int* in_sizes, int n_in,
                              void* d_out, int out_size)
{
    const float* x  = (const float*)d_in[0];
    const int*   am = (const int*)  d_in[1];
    const float* Wq = (const float*)d_in[2];
    const float* bq = (const float*)d_in[3];
    const float* Wk = (const float*)d_in[4];
    const float* bk = (const float*)d_in[5];
    const float* Wv = (const float*)d_in[6];
    const float* bv = (const float*)d_in[7];
    const float* Wo = (const float*)d_in[8];
    const float* bo = (const float*)d_in[9];

    float* out   = (float*)d_out;
    float* attnW = out + (size_t)NROWS * D_MODEL;

    cudaFuncSetAttribute((const void*)attn_pv_kernel,
                         cudaFuncAttributeMaxDynamicSharedMemorySize, PV_SMEM);

    const int splitBlocks = (NROWS * D_MODEL) / (256 * 4);

    split_kernel<<<splitBlocks, 256>>>(x, -1);

    dim3 gW3(D_MODEL / 32, D_MODEL / 32, 3);
    wsplit_kernel<<<gW3, 256>>>(Wq, Wk, Wv);
    dim3 gG3(D_MODEL / 128, NROWS / 128, 3);
    tc_gemm_kernel<<<gG3, 256>>>(bq, bk, bv, nullptr, 1);

    dim3 gAttn(SEQ / 64, NUM_HEADS, BATCH);     // (32, 16, 2)
    attn_stats_kernel<<<gAttn, 256>>>(am);
    attn_pv_kernel<<<gAttn, 256, PV_SMEM>>>(am, attnW);

    split_kernel<<<splitBlocks, 256>>>(nullptr, 3);
    dim3 gW1(D_MODEL / 32, D_MODEL / 32, 1);
    wsplit_kernel<<<gW1, 256>>>(Wo, Wo, Wo);
    dim3 gG1(D_MODEL / 128, NROWS / 128, 1);
    tc_gemm_kernel<<<gG1, 256>>>(bo, bo, bo, out, 0);
}

// round 17
// speedup vs baseline: 3.1780x; 1.0008x over previous
#include <cuda_runtime.h>
#include <cuda_bf16.h>
#include <cstdint>
#include <math.h>

#define D_MODEL   1024
#define NUM_HEADS 16
#define HEAD_DIM  64
#define BATCH     2
#define SEQ       2048
#define NROWS     (BATCH * SEQ)   // 4096
#define D2        ((size_t)D_MODEL * D_MODEL)

// ---------------------------------------------------------------------------
// Scratch (device globals; no runtime allocation allowed)
// ---------------------------------------------------------------------------
__device__ float g_AO[(size_t)NROWS * D_MODEL];
__device__ __nv_bfloat16 g_xh[(size_t)NROWS * D_MODEL];
__device__ __nv_bfloat16 g_xl[(size_t)NROWS * D_MODEL];
__device__ __nv_bfloat16 g_wh[4 * D2];
__device__ __nv_bfloat16 g_wl[4 * D2];
__device__ __nv_bfloat16 g_Qh[(size_t)NROWS * D_MODEL];
__device__ __nv_bfloat16 g_Ql[(size_t)NROWS * D_MODEL];
__device__ __nv_bfloat16 g_Kh[(size_t)NROWS * D_MODEL];
__device__ __nv_bfloat16 g_Kl[(size_t)NROWS * D_MODEL];
__device__ __nv_bfloat16 g_Vh[(size_t)NROWS * D_MODEL];
__device__ __nv_bfloat16 g_Vl[(size_t)NROWS * D_MODEL];
__device__ float g_m [(size_t)BATCH * NUM_HEADS * SEQ];
__device__ float g_il[(size_t)BATCH * NUM_HEADS * SEQ];

// ---------------------------------------------------------------------------
// HMMA helpers (mma.sync bf16, base sm_103 target)
// ---------------------------------------------------------------------------
__device__ __forceinline__ uint32_t smem_u32(const void* p) {
    uint32_t a;
    asm("{ .reg .u64 t; cvta.to.shared.u64 t, %1; cvt.u32.u64 %0, t; }"
        : "=r"(a) : "l"(p));
    return a;
}
__device__ __forceinline__ void ldmatrix_x4(uint32_t& r0, uint32_t& r1,
                                            uint32_t& r2, uint32_t& r3,
                                            uint32_t addr) {
    asm volatile("ldmatrix.sync.aligned.m8n8.x4.shared.b16 {%0,%1,%2,%3}, [%4];"
                 : "=r"(r0), "=r"(r1), "=r"(r2), "=r"(r3) : "r"(addr));
}
__device__ __forceinline__ void ldmatrix_x2(uint32_t& r0, uint32_t& r1,
                                            uint32_t addr) {
    asm volatile("ldmatrix.sync.aligned.m8n8.x2.shared.b16 {%0,%1}, [%2];"
                 : "=r"(r0), "=r"(r1) : "r"(addr));
}
__device__ __forceinline__ void ldmatrix_x2_trans(uint32_t& r0, uint32_t& r1,
                                                  uint32_t addr) {
    asm volatile("ldmatrix.sync.aligned.m8n8.x2.trans.shared.b16 {%0,%1}, [%2];"
                 : "=r"(r0), "=r"(r1) : "r"(addr));
}
__device__ __forceinline__ void mma_bf16(float* d, const uint32_t* a,
                                         const uint32_t* b) {
    asm volatile(
        "mma.sync.aligned.m16n8k16.row.col.f32.bf16.bf16.f32 "
        "{%0,%1,%2,%3}, {%4,%5,%6,%7}, {%8,%9}, {%0,%1,%2,%3};"
        : "+f"(d[0]), "+f"(d[1]), "+f"(d[2]), "+f"(d[3])
        : "r"(a[0]), "r"(a[1]), "r"(a[2]), "r"(a[3]), "r"(b[0]), "r"(b[1]));
}
__device__ __forceinline__ void split_bf16(float v, __nv_bfloat16& h,
                                           __nv_bfloat16& l) {
    h = __float2bfloat16(v);
    l = __float2bfloat16(v - __bfloat162float(h));
}

// ---------------------------------------------------------------------------
// Split fp32 -> (hi, lo) bf16. sel=-1: src pointer (x); sel>=0: g_AO.
// ---------------------------------------------------------------------------
__global__ __launch_bounds__(256)
void split_kernel(const float* src, int sel)
{
    const float* A = (sel >= 0) ? g_AO : src;
    size_t i4 = ((size_t)blockIdx.x * 256 + threadIdx.x) * 4;
    float4 v = *(const float4*)&A[i4];
    float vs[4] = {v.x, v.y, v.z, v.w};
    __nv_bfloat16 h[4], l[4];
#pragma unroll
    for (int j = 0; j < 4; j++) split_bf16(vs[j], h[j], l[j]);
    __nv_bfloat162 h0 = {h[0], h[1]}, h1 = {h[2], h[3]};
    __nv_bfloat162 l0 = {l[0], l[1]}, l1 = {l[2], l[3]};
    uint2 uh, ul;
    uh.x = *(uint32_t*)&h0; uh.y = *(uint32_t*)&h1;
    ul.x = *(uint32_t*)&l0; ul.y = *(uint32_t*)&l1;
    *(uint2*)&g_xh[i4] = uh;
    *(uint2*)&g_xl[i4] = ul;
}

// ---------------------------------------------------------------------------
// W [K,N] fp32 -> transposed (hi, lo) bf16 [N,K]; slot = blockIdx.z (0..3).
// ---------------------------------------------------------------------------
__global__ __launch_bounds__(256)
void wsplit_kernel(const float* w0, const float* w1, const float* w2,
                   const float* w3)
{
    __shared__ float ts[32][33];
    const int z = blockIdx.z;
    const float* W = (z == 0) ? w0 : (z == 1) ? w1 : (z == 2) ? w2 : w3;
    __nv_bfloat16* dh = g_wh + (size_t)z * D2;
    __nv_bfloat16* dl = g_wl + (size_t)z * D2;
    const int tx = threadIdx.x & 31, ty = threadIdx.x >> 5;
    const int n0 = blockIdx.x * 32, k0 = blockIdx.y * 32;
#pragma unroll
    for (int i = 0; i < 4; i++)
        ts[ty + i * 8][tx] = W[(size_t)(k0 + ty + i * 8) * D_MODEL + n0 + tx];
    __syncthreads();
#pragma unroll
    for (int i = 0; i < 4; i++) {
        float a = ts[tx][ty + i * 8];
        __nv_bfloat16 h, l;
        split_bf16(a, h, l);
        size_t o = (size_t)(n0 + ty + i * 8) * D_MODEL + k0 + tx;
        dh[o] = h; dl[o] = l;
    }
}

// ---------------------------------------------------------------------------
// HMMA bf16x3 GEMM. qkvMode!=0: weight slot blockIdx.z, bias z, bf16 dest
// Q/K/V. qkvMode==0: weight slot 3, bias b0, fp32 out C.
// ---------------------------------------------------------------------------
#define KC 32
#define NCHUNK (D_MODEL / KC)
#define SSTRIDE 40

__global__ __launch_bounds__(256)
void tc_gemm_kernel(const float* __restrict__ b0, const float* __restrict__ b1,
                    const float* __restrict__ b2, float* C, int qkvMode)
{
    __shared__ __nv_bfloat16 sAh[128][SSTRIDE];
    __shared__ __nv_bfloat16 sAl[128][SSTRIDE];
    __shared__ __nv_bfloat16 sBh[128][SSTRIDE];
    __shared__ __nv_bfloat16 sBl[128][SSTRIDE];

    const int z = qkvMode ? blockIdx.z : 0;
    const int wslot = qkvMode ? blockIdx.z : 3;
    const float* bias = (z == 0) ? b0 : (z == 1) ? b1 : b2;
    const __nv_bfloat16* wh = g_wh + (size_t)wslot * D2;
    const __nv_bfloat16* wl = g_wl + (size_t)wslot * D2;

    const int tid  = threadIdx.x;
    const int wid  = tid >> 5;
    const int lane = tid & 31;
    const int wm   = (wid & 1) * 64;
    const int wn   = (wid >> 1) * 32;

    const int bn = blockIdx.x * 128;
    const int bm = blockIdx.y * 128;

    float acc[4][4][4];
#pragma unroll
    for (int i = 0; i < 4; i++)
#pragma unroll
        for (int j = 0; j < 4; j++)
#pragma unroll
            for (int t = 0; t < 4; t++) acc[i][j][t] = 0.f;

    const int ldRow = tid >> 2;
    const int ldSeg = tid & 3;

    const uint32_t aAh = smem_u32(sAh), aAl = smem_u32(sAl);
    const uint32_t aBh = smem_u32(sBh), aBl = smem_u32(sBl);
    const int aRow = wm + (lane & 15);
    const int aKh  = (lane >> 4);
    const int bRow = wn + (lane & 7);
    const int bKh  = (lane >> 3) & 1;

    for (int c = 0; c < NCHUNK; c++) {
        const int k0 = c * KC;
        __syncthreads();
#pragma unroll
        for (int u = 0; u < 2; u++) {
            const int r = ldRow + u * 64;
            const size_t gA = (size_t)(bm + r) * D_MODEL + k0 + ldSeg * 8;
            const size_t gB = (size_t)(bn + r) * D_MODEL + k0 + ldSeg * 8;
            *(uint4*)&sAh[r][ldSeg * 8] = *(const uint4*)&g_xh[gA];
            *(uint4*)&sAl[r][ldSeg * 8] = *(const uint4*)&g_xl[gA];
            *(uint4*)&sBh[r][ldSeg * 8] = *(const uint4*)&wh[gB];
            *(uint4*)&sBl[r][ldSeg * 8] = *(const uint4*)&wl[gB];
        }
        __syncthreads();

#pragma unroll
        for (int step = 0; step < 2; step++) {
            const uint32_t kByteA = (uint32_t)(step * 32 + aKh * 16);
            const uint32_t kByteB = (uint32_t)(step * 32 + bKh * 16);

            uint32_t Bh[4][2], Bl[4][2];
#pragma unroll
            for (int nt = 0; nt < 4; nt++) {
                uint32_t off = (uint32_t)(bRow + nt * 8) * (SSTRIDE * 2) + kByteB;
                ldmatrix_x2(Bh[nt][0], Bh[nt][1], aBh + off);
                ldmatrix_x2(Bl[nt][0], Bl[nt][1], aBl + off);
            }
#pragma unroll
            for (int mt = 0; mt < 4; mt++) {
                uint32_t off = (uint32_t)(aRow + mt * 16) * (SSTRIDE * 2) + kByteA;
                uint32_t Ah[4], Al[4];
                ldmatrix_x4(Ah[0], Ah[1], Ah[2], Ah[3], aAh + off);
                ldmatrix_x4(Al[0], Al[1], Al[2], Al[3], aAl + off);
#pragma unroll
                for (int nt = 0; nt < 4; nt++) {
                    mma_bf16(acc[mt][nt], Ah, Bh[nt]);
                    mma_bf16(acc[mt][nt], Al, Bh[nt]);
                    mma_bf16(acc[mt][nt], Ah, Bl[nt]);
                }
            }
        }
    }

    __nv_bfloat16* dh = (z == 0) ? g_Qh : (z == 1) ? g_Kh : g_Vh;
    __nv_bfloat16* dl = (z == 0) ? g_Ql : (z == 1) ? g_Kl : g_Vl;

    const int cg = lane >> 2;
    const int ct = (lane & 3) * 2;
#pragma unroll
    for (int mt = 0; mt < 4; mt++) {
#pragma unroll
        for (int nt = 0; nt < 4; nt++) {
            const int col = bn + wn + nt * 8 + ct;
            const float2 bv = *(const float2*)&bias[col];
            const int r0 = bm + wm + mt * 16 + cg;
            float e[2][2] = {{acc[mt][nt][0] + bv.x, acc[mt][nt][1] + bv.y},
                             {acc[mt][nt][2] + bv.x, acc[mt][nt][3] + bv.y}};
            if (!qkvMode) {
                *(float2*)&C[(size_t)r0 * D_MODEL + col]       = *(float2*)e[0];
                *(float2*)&C[(size_t)(r0 + 8) * D_MODEL + col] = *(float2*)e[1];
            } else {
#pragma unroll
                for (int u = 0; u < 2; u++) {
                    __nv_bfloat16 h0, l0, h1, l1;
                    split_bf16(e[u][0], h0, l0);
                    split_bf16(e[u][1], h1, l1);
                    __nv_bfloat162 ph = {h0, h1}, pl = {l0, l1};
                    size_t o = (size_t)(r0 + u * 8) * D_MODEL + col;
                    *(__nv_bfloat162*)&dh[o] = ph;
                    *(__nv_bfloat162*)&dl[o] = pl;
                }
            }
        }
    }
}

// ---------------------------------------------------------------------------
// Attention pass 1 (stats only): 256 threads, 8 warps (2m x 4n), warp tile
// 32x32, CTA tile 64q x 128k (R15-proven index math, stores removed).
// Computes exact online (m, 1/l) per row -> g_m / g_il.
// Dynamic smem 55296 B: sQh/sQl [64][72], sKh/sKl [128][72].
// ---------------------------------------------------------------------------
#define ATS 72
#define STATS_SMEM ((64 * ATS * 2 + 128 * ATS * 2) * 2)   // 55296

__global__ __launch_bounds__(256)
void attn_stats_kernel(const int* __restrict__ mask)
{
    extern __shared__ char dynS[];
    __nv_bfloat16* sQh = (__nv_bfloat16*)dynS;
    __nv_bfloat16* sQl = sQh + 64 * ATS;
    __nv_bfloat16* sKh = sQl + 64 * ATS;
    __nv_bfloat16* sKl = sKh + 128 * ATS;
    __shared__ int   maskS[128];
    __shared__ float sM[4][64], sL[4][64];

    const int qt = blockIdx.x, h = blockIdx.y, b = blockIdx.z;
    const int tid  = threadIdx.x;
    const int wid  = tid >> 5;
    const int lane = tid & 31;
    const int wm   = (wid & 1) * 32;     // 2 m-groups
    const int wn   = (wid >> 1) * 32;    // 4 n-groups -> 128 k
    const int q0   = qt * 64;

    const uint32_t aQh = smem_u32(sQh), aQl = smem_u32(sQl);
    const uint32_t aKh = smem_u32(sKh), aKl = smem_u32(sKl);

    // stage Q once: 64 rows x 64 bf16
    {
        const int r = tid >> 2, c = (tid & 3) * 16;
        const size_t g = (size_t)(b * SEQ + q0 + r) * D_MODEL + h * HEAD_DIM + c;
        *(uint4*)&sQh[r * ATS + c]     = *(const uint4*)&g_Qh[g];
        *(uint4*)&sQh[r * ATS + c + 8] = *(const uint4*)&g_Qh[g + 8];
        *(uint4*)&sQl[r * ATS + c]     = *(const uint4*)&g_Ql[g];
        *(uint4*)&sQl[r * ATS + c + 8] = *(const uint4*)&g_Ql[g + 8];
    }

    const size_t rowBase = (size_t)(b * NUM_HEADS + h) * SEQ + q0;

    float rm[4], rl[4];
#pragma unroll
    for (int i = 0; i < 4; i++) { rm[i] = -3.0e38f; rl[i] = 0.f; }

    for (int ks = 0; ks < SEQ; ks += 128) {
        __syncthreads();
        // stage K: 128 rows x 64 bf16
        {
            const int r = tid >> 1, c = (tid & 1) * 32;
            const size_t g = (size_t)(b * SEQ + ks + r) * D_MODEL
                           + h * HEAD_DIM + c;
#pragma unroll
            for (int j = 0; j < 4; j++)
                *(uint4*)&sKh[r * ATS + c + j * 8] = *(const uint4*)&g_Kh[g + j * 8];
#pragma unroll
            for (int j = 0; j < 4; j++)
                *(uint4*)&sKl[r * ATS + c + j * 8] = *(const uint4*)&g_Kl[g + j * 8];
            if (tid < 128) maskS[tid] = mask[b * SEQ + ks + tid];
        }
        __syncthreads();

        float acc[2][4][4];
#pragma unroll
        for (int i = 0; i < 2; i++)
#pragma unroll
            for (int j = 0; j < 4; j++)
#pragma unroll
                for (int t = 0; t < 4; t++) acc[i][j][t] = 0.f;

        const uint32_t aRowOff = (uint32_t)(wm + (lane & 15)) * (ATS * 2);
        const uint32_t akh = (uint32_t)(lane >> 4) * 16;
        const uint32_t bRowOff = (uint32_t)(wn + (lane & 7)) * (ATS * 2);
        const uint32_t bkh = (uint32_t)((lane >> 3) & 1) * 16;
#pragma unroll
        for (int st = 0; st < 4; st++) {
            uint32_t Bh[4][2], Bl[4][2];
#pragma unroll
            for (int nt = 0; nt < 4; nt++) {
                uint32_t off = bRowOff + (uint32_t)(nt * 8) * (ATS * 2)
                             + (uint32_t)(st * 32) + bkh;
                ldmatrix_x2(Bh[nt][0], Bh[nt][1], aKh + off);
                ldmatrix_x2(Bl[nt][0], Bl[nt][1], aKl + off);
            }
#pragma unroll
            for (int mt = 0; mt < 2; mt++) {
                uint32_t off = aRowOff + (uint32_t)(mt * 16) * (ATS * 2)
                             + (uint32_t)(st * 32) + akh;
                uint32_t Ah[4], Al[4];
                ldmatrix_x4(Ah[0], Ah[1], Ah[2], Ah[3], aQh + off);
                ldmatrix_x4(Al[0], Al[1], Al[2], Al[3], aQl + off);
#pragma unroll
                for (int nt = 0; nt < 4; nt++) {
                    mma_bf16(acc[mt][nt], Ah, Bh[nt]);
                    mma_bf16(acc[mt][nt], Al, Bh[nt]);
                    mma_bf16(acc[mt][nt], Ah, Bl[nt]);
                }
            }
        }

        // scale + mask, update online (m,l) — no stores
        const int cg = lane >> 2, ct = (lane & 3) * 2;
#pragma unroll
        for (int mt = 0; mt < 2; mt++) {
#pragma unroll
            for (int u = 0; u < 2; u++) {
                const int idx = mt * 2 + u;
                float v[8];
#pragma unroll
                for (int nt = 0; nt < 4; nt++) {
                    const int col = wn + nt * 8 + ct;
                    const bool m0 = (maskS[col] == 0), m1 = (maskS[col + 1] == 0);
                    v[nt * 2 + 0] = m0 ? -3.0e38f : acc[mt][nt][u * 2 + 0] * 0.125f;
                    v[nt * 2 + 1] = m1 ? -3.0e38f : acc[mt][nt][u * 2 + 1] * 0.125f;
                }
                float tm = v[0];
#pragma unroll
                for (int j = 1; j < 8; j++) tm = fmaxf(tm, v[j]);
                tm = fmaxf(tm, __shfl_xor_sync(0xffffffffu, tm, 1));
                tm = fmaxf(tm, __shfl_xor_sync(0xffffffffu, tm, 2));
                float nm = fmaxf(rm[idx], tm);
                float ps = 0.f;
#pragma unroll
                for (int j = 0; j < 8; j++) ps += __expf(v[j] - nm);
                ps += __shfl_xor_sync(0xffffffffu, ps, 1);
                ps += __shfl_xor_sync(0xffffffffu, ps, 2);
                rl[idx] = rl[idx] * __expf(rm[idx] - nm) + ps;
                rm[idx] = nm;
            }
        }
    }

    // combine over the 4 column groups
    const int g = wid >> 1;
    if ((lane & 3) == 0) {
        const int cg = lane >> 2;
#pragma unroll
        for (int mt = 0; mt < 2; mt++)
#pragma unroll
            for (int u = 0; u < 2; u++) {
                const int r = wm + mt * 16 + cg + u * 8;
                sM[g][r] = rm[mt * 2 + u];
                sL[g][r] = rl[mt * 2 + u];
            }
    }
    __syncthreads();
    if (tid < 64) {
        float M = sM[0][tid];
#pragma unroll
        for (int gg = 1; gg < 4; gg++) M = fmaxf(M, sM[gg][tid]);
        float L = 0.f;
#pragma unroll
        for (int gg = 0; gg < 4; gg++)
            L += sL[gg][tid] * __expf(sM[gg][tid] - M);
        g_m [rowBase + tid] = M;
        g_il[rowBase + tid] = 1.0f / L;
    }
}

// ---------------------------------------------------------------------------
// Attention pass 2 (unchanged R16-proven): recompute S, P = exp(S-m)*il,
// write final P fp32 to attnW, stage Ph/Pl, accumulate O = P @ V -> g_AO.
// ---------------------------------------------------------------------------
#define PVBUF (64 * ATS)
#define PV_SMEM (8 * PVBUF * 2)   // 73728 bytes

__global__ __launch_bounds__(256)
void attn_pv_kernel(const int* __restrict__ mask, float* __restrict__ attnW)
{
    extern __shared__ char dynS[];
    __nv_bfloat16* sQh = (__nv_bfloat16*)dynS;
    __nv_bfloat16* sQl = sQh + PVBUF;
    __nv_bfloat16* sKh = sQl + PVBUF;
    __nv_bfloat16* sKl = sKh + PVBUF;
    __nv_bfloat16* sVh = sKl + PVBUF;
    __nv_bfloat16* sVl = sVh + PVBUF;
    __nv_bfloat16* sPh = sVl + PVBUF;
    __nv_bfloat16* sPl = sPh + PVBUF;
    __shared__ int maskS[64];

    const int qt = blockIdx.x, h = blockIdx.y, b = blockIdx.z;
    const int tid  = threadIdx.x;
    const int wid  = tid >> 5;
    const int lane = tid & 31;
    const int wm   = (wid & 1) * 32;
    const int wk   = (wid >> 1) * 16;
    const int wd   = (wid >> 1) * 16;
    const int q0   = qt * 64;

    const uint32_t aQh = smem_u32(sQh), aQl = smem_u32(sQl);
    const uint32_t aKh = smem_u32(sKh), aKl = smem_u32(sKl);
    const uint32_t aVh = smem_u32(sVh), aVl = smem_u32(sVl);
    const uint32_t aPh = smem_u32(sPh), aPl = smem_u32(sPl);

    const size_t rowBase = (size_t)(b * NUM_HEADS + h) * SEQ + q0;

    {
        const int r = tid >> 2, c = (tid & 3) * 16;
        const size_t g = (size_t)(b * SEQ + q0 + r) * D_MODEL + h * HEAD_DIM + c;
        *(uint4*)&sQh[r * ATS + c]     = *(const uint4*)&g_Qh[g];
        *(uint4*)&sQh[r * ATS + c + 8] = *(const uint4*)&g_Qh[g + 8];
        *(uint4*)&sQl[r * ATS + c]     = *(const uint4*)&g_Ql[g];
        *(uint4*)&sQl[r * ATS + c + 8] = *(const uint4*)&g_Ql[g + 8];
    }

    const int cg = lane >> 2, ct = (lane & 3) * 2;

    float pm[4], pil[4];
#pragma unroll
    for (int mt = 0; mt < 2; mt++)
#pragma unroll
        for (int u = 0; u < 2; u++) {
            const int r = wm + mt * 16 + cg + u * 8;
            pm [mt * 2 + u] = g_m [rowBase + r];
            pil[mt * 2 + u] = g_il[rowBase + r];
        }

    float pvacc[2][2][4];
#pragma unroll
    for (int i = 0; i < 2; i++)
#pragma unroll
        for (int j = 0; j < 2; j++)
#pragma unroll
            for (int t = 0; t < 4; t++) pvacc[i][j][t] = 0.f;

    for (int ks = 0; ks < SEQ; ks += 64) {
        __syncthreads();
        {
            const int r = tid >> 2, c = (tid & 3) * 16;
            const size_t gk = (size_t)(b * SEQ + ks + r) * D_MODEL + h * HEAD_DIM + c;
            *(uint4*)&sKh[r * ATS + c]     = *(const uint4*)&g_Kh[gk];
            *(uint4*)&sKh[r * ATS + c + 8] = *(const uint4*)&g_Kh[gk + 8];
            *(uint4*)&sKl[r * ATS + c]     = *(const uint4*)&g_Kl[gk];
            *(uint4*)&sKl[r * ATS + c + 8] = *(const uint4*)&g_Kl[gk + 8];
            *(uint4*)&sVh[r * ATS + c]     = *(const uint4*)&g_Vh[gk];
            *(uint4*)&sVh[r * ATS + c + 8] = *(const uint4*)&g_Vh[gk + 8];
            *(uint4*)&sVl[r * ATS + c]     = *(const uint4*)&g_Vl[gk];
            *(uint4*)&sVl[r * ATS + c + 8] = *(const uint4*)&g_Vl[gk + 8];
            if (tid < 64) maskS[tid] = mask[b * SEQ + ks + tid];
        }
        __syncthreads();

        float sacc[2][2][4];
#pragma unroll
        for (int i = 0; i < 2; i++)
#pragma unroll
            for (int j = 0; j < 2; j++)
#pragma unroll
                for (int t = 0; t < 4; t++) sacc[i][j][t] = 0.f;

#pragma unroll
        for (int st = 0; st < 4; st++) {
            const uint32_t kbA = (uint32_t)(st * 32 + (lane >> 4) * 16);
            const uint32_t kbB = (uint32_t)(st * 32 + ((lane >> 3) & 1) * 16);
            uint32_t Bh[2][2], Bl[2][2];
#pragma unroll
            for (int nt = 0; nt < 2; nt++) {
                uint32_t off = (uint32_t)(wk + nt * 8 + (lane & 7)) * (ATS * 2) + kbB;
                ldmatrix_x2(Bh[nt][0], Bh[nt][1], aKh + off);
                ldmatrix_x2(Bl[nt][0], Bl[nt][1], aKl + off);
            }
#pragma unroll
            for (int mt = 0; mt < 2; mt++) {
                uint32_t off = (uint32_t)(wm + mt * 16 + (lane & 15)) * (ATS * 2) + kbA;
                uint32_t Ah[4], Al[4];
                ldmatrix_x4(Ah[0], Ah[1], Ah[2], Ah[3], aQh + off);
                ldmatrix_x4(Al[0], Al[1], Al[2], Al[3], aQl + off);
#pragma unroll
                for (int nt = 0; nt < 2; nt++) {
                    mma_bf16(sacc[mt][nt], Ah, Bh[nt]);
                    mma_bf16(sacc[mt][nt], Al, Bh[nt]);
                    mma_bf16(sacc[mt][nt], Ah, Bl[nt]);
                }
            }
        }

#pragma unroll
        for (int mt = 0; mt < 2; mt++) {
#pragma unroll
            for (int nt = 0; nt < 2; nt++) {
                const int col = wk + nt * 8 + ct;
                const bool m0 = (maskS[col] == 0), m1 = (maskS[col + 1] == 0);
#pragma unroll
                for (int u = 0; u < 2; u++) {
                    const int idx = mt * 2 + u;
                    const int rq  = wm + mt * 16 + cg + u * 8;
                    float p0 = m0 ? 0.f
                        : __expf(sacc[mt][nt][u * 2 + 0] * 0.125f - pm[idx]) * pil[idx];
                    float p1 = m1 ? 0.f
                        : __expf(sacc[mt][nt][u * 2 + 1] * 0.125f - pm[idx]) * pil[idx];
                    *(float2*)&attnW[(rowBase + rq) * SEQ + ks + col] =
                        make_float2(p0, p1);
                    __nv_bfloat16 h0, l0, h1, l1;
                    split_bf16(p0, h0, l0);
                    split_bf16(p1, h1, l1);
                    __nv_bfloat162 ph = {h0, h1}, pl = {l0, l1};
                    *(__nv_bfloat162*)&sPh[rq * ATS + col] = ph;
                    *(__nv_bfloat162*)&sPl[rq * ATS + col] = pl;
                }
            }
        }
        __syncthreads();

        const uint32_t aRowOff = (uint32_t)(wm + (lane & 15)) * (ATS * 2);
        const uint32_t akh = (uint32_t)(lane >> 4) * 16;
#pragma unroll
        for (int st = 0; st < 4; st++) {
            uint32_t Bh[2][2], Bl[2][2];
#pragma unroll
            for (int nt = 0; nt < 2; nt++) {
                uint32_t off = (uint32_t)(st * 16 + (lane & 15)) * (ATS * 2)
                             + (uint32_t)(wd + nt * 8) * 2;
                ldmatrix_x2_trans(Bh[nt][0], Bh[nt][1], aVh + off);
                ldmatrix_x2_trans(Bl[nt][0], Bl[nt][1], aVl + off);
            }
#pragma unroll
            for (int mt = 0; mt < 2; mt++) {
                uint32_t off = aRowOff + (uint32_t)(mt * 16) * (ATS * 2)
                             + (uint32_t)(st * 32) + akh;
                uint32_t Ah[4], Al[4];
                ldmatrix_x4(Ah[0], Ah[1], Ah[2], Ah[3], aPh + off);
                ldmatrix_x4(Al[0], Al[1], Al[2], Al[3], aPl + off);
#pragma unroll
                for (int nt = 0; nt < 2; nt++) {
                    mma_bf16(pvacc[mt][nt], Ah, Bh[nt]);
                    mma_bf16(pvacc[mt][nt], Al, Bh[nt]);
                    mma_bf16(pvacc[mt][nt], Ah, Bl[nt]);
                }
            }
        }
    }

#pragma unroll
    for (int mt = 0; mt < 2; mt++) {
#pragma unroll
        for (int nt = 0; nt < 2; nt++) {
            const int cd = wd + nt * 8 + ct;
#pragma unroll
            for (int u = 0; u < 2; u++) {
                const int rq = q0 + wm + mt * 16 + cg + u * 8;
                float2 v = {pvacc[mt][nt][u * 2 + 0], pvacc[mt][nt][u * 2 + 1]};
                *(float2*)&g_AO[(size_t)(b * SEQ + rq) * D_MODEL
                                + h * HEAD_DIM + cd] = v;
            }
        }
    }
}

// ---------------------------------------------------------------------------
// Launch
// ---------------------------------------------------------------------------
extern "C" void kernel_launch(void* const* d_in, const int* in_sizes, int n_in,
                              void* d_out, int out_size)
{
    const float* x  = (const float*)d_in[0];
    const int*   am = (const int*)  d_in[1];
    const float* Wq = (const float*)d_in[2];
    const float* bq = (const float*)d_in[3];
    const float* Wk = (const float*)d_in[4];
    const float* bk = (const float*)d_in[5];
    const float* Wv = (const float*)d_in[6];
    const float* bv = (const float*)d_in[7];
    const float* Wo = (const float*)d_in[8];
    const float* bo = (const float*)d_in[9];

    float* out   = (float*)d_out;
    float* attnW = out + (size_t)NROWS * D_MODEL;

    cudaFuncSetAttribute((const void*)attn_stats_kernel,
                         cudaFuncAttributeMaxDynamicSharedMemorySize, STATS_SMEM);
    cudaFuncSetAttribute((const void*)attn_pv_kernel,
                         cudaFuncAttributeMaxDynamicSharedMemorySize, PV_SMEM);

    const int splitBlocks = (NROWS * D_MODEL) / (256 * 4);

    split_kernel<<<splitBlocks, 256>>>(x, -1);

    dim3 gW4(D_MODEL / 32, D_MODEL / 32, 4);
    wsplit_kernel<<<gW4, 256>>>(Wq, Wk, Wv, Wo);
    dim3 gG3(D_MODEL / 128, NROWS / 128, 3);
    tc_gemm_kernel<<<gG3, 256>>>(bq, bk, bv, nullptr, 1);

    dim3 gAttn(SEQ / 64, NUM_HEADS, BATCH);     // (32, 16, 2)
    attn_stats_kernel<<<gAttn, 256, STATS_SMEM>>>(am);
    attn_pv_kernel<<<gAttn, 256, PV_SMEM>>>(am, attnW);

    split_kernel<<<splitBlocks, 256>>>(nullptr, 3);
    dim3 gG1(D_MODEL / 128, NROWS / 128, 1);
    tc_gemm_kernel<<<gG1, 256>>>(bo, bo, bo, out, 0);
}